// round 13
// baseline (speedup 1.0000x reference)
#include <cuda_runtime.h>
#include <math.h>
#include <stdint.h>

#define NTOK 2048
#define DDIM 1024
#define NEXP 8
#define FDIM 2048
#define NASS (NTOK * 2)

// GEMM tiling: CTA 128x256, warp 64x32 (16 warps = 512 threads), BK=64
#define BM 128
#define BN 256
#define BK 64
#define THREADS 512

// fragment-major smem layout (double-buffered), BK=64 => ks 0..7:
//  A: 64 groups (MI 0..7 x ks 0..7), each 33 x 16B lines
//  B: 256 groups (NI 0..31 x ks 0..7), each 33 x 8B lines
#define A_BUF_BYTES (64 * 33 * 16)      // 33792
#define B_BUF_BYTES (256 * 33 * 8)      // 67584
#define STAGE_BYTES (A_BUF_BYTES + B_BUF_BYTES)   // 101376
#define SM_META     (2 * STAGE_BYTES)             // 202752
#define SM_TOTAL    (SM_META + 512 * 3)           // 204288 <= 227KB

// wave-2 constant delta for B only (B swizzle has no ks term)
#define B_W2_OFF (4 * 33 * 8)           // +4 groups * 33*8

// ---------------- scratch (device globals) ---------------------------------
__device__ int   g_cnt[NEXP];
__device__ int   g_rows[NEXP][NTOK];
__device__ float g_gate[NASS];
__device__ float g_act[(size_t)NASS * FDIM];   // 32 MB
__device__ float g_y[(size_t)NASS * DDIM];     // 16 MB

// ---------------- helpers ---------------------------------------------------
__device__ __forceinline__ unsigned f2tf(float f) {   // RNA fp32 -> tf32 bits
    unsigned u;
    asm("cvt.rna.tf32.f32 %0, %1;" : "=r"(u) : "f"(f));
    return u;
}
__device__ __forceinline__ void mma_tf32(float* c, const unsigned* a, const unsigned* b) {
    asm volatile(
        "mma.sync.aligned.m16n8k8.row.col.f32.tf32.tf32.f32 "
        "{%0,%1,%2,%3}, {%4,%5,%6,%7}, {%8,%9}, {%0,%1,%2,%3};"
        : "+f"(c[0]), "+f"(c[1]), "+f"(c[2]), "+f"(c[3])
        : "r"(a[0]), "r"(a[1]), "r"(a[2]), "r"(a[3]), "r"(b[0]), "r"(b[1]));
}

// ---------------- kernel 0: zero expert counters ---------------------------
__global__ void k_zero() {
    if (threadIdx.x < NEXP) g_cnt[threadIdx.x] = 0;
}

// ---------------- kernel 1: router (one warp per token) --------------------
__global__ void k_router(const float* __restrict__ x, const float* __restrict__ Wr) {
    int warp = (blockIdx.x * blockDim.x + threadIdx.x) >> 5;
    int lane = threadIdx.x & 31;
    if (warp >= NTOK) return;
    const float* xr = x + (size_t)warp * DDIM;

    float acc[NEXP];
#pragma unroll
    for (int e = 0; e < NEXP; e++) acc[e] = 0.f;
    for (int i = lane; i < DDIM; i += 32) {
        float xv = xr[i];
#pragma unroll
        for (int e = 0; e < NEXP; e++) acc[e] += xv * Wr[e * DDIM + i];
    }
#pragma unroll
    for (int e = 0; e < NEXP; e++) {
#pragma unroll
        for (int off = 16; off; off >>= 1)
            acc[e] += __shfl_xor_sync(0xffffffffu, acc[e], off);
    }
    if (lane == 0) {
        int i0 = 0;
#pragma unroll
        for (int e = 1; e < NEXP; e++)
            if (acc[e] > acc[i0]) i0 = e;
        int i1 = -1;
#pragma unroll
        for (int e = 0; e < NEXP; e++) {
            if (e == i0) continue;
            if (i1 < 0 || acc[e] > acc[i1]) i1 = e;
        }
        float ex  = expf(acc[i1] - acc[i0]);
        float inv = 1.f / (1.f + ex);
        int p0 = atomicAdd(&g_cnt[i0], 1);
        g_rows[i0][p0] = 2 * warp;
        int p1 = atomicAdd(&g_cnt[i1], 1);
        g_rows[i1][p1] = 2 * warp + 1;
        g_gate[2 * warp]     = inv;
        g_gate[2 * warp + 1] = ex * inv;
    }
}

// ---------------- grouped GEMM: legacy mma.sync tf32, frag-major smem ------
// CTA 128x256; 16 warps 2(m) x 8(n); warp 64x32. BK=64, double-buffered,
// two-wave staging. Wave-2 A offsets carry the CORRECT ks+4 swizzle (R12 bug).
template <int KTOT, int ROWSHIFT, int CSTRIDE, bool SQRELU, bool GATE>
__global__ __launch_bounds__(THREADS, 1)
void k_gemm(const float* __restrict__ Asrc, const float* __restrict__ Bsrc) {
    extern __shared__ char smem[];
    const int e   = blockIdx.z;
    const int cnt = g_cnt[e];
    const int m0  = blockIdx.y * BM;
    if (m0 >= cnt) return;
    const int n0  = blockIdx.x * BN;
    const int tid  = threadIdx.x;
    const int wid  = tid >> 5;
    const int lane = tid & 31;
    const int g    = lane >> 2;
    const int t    = lane & 3;
    const int wm   = wid >> 3;     // 0..1
    const int wn   = wid & 7;      // 0..7

    int*   s_a   = (int*)(smem + SM_META);
    int*   s_row = (int*)(smem + SM_META + 512);
    float* s_g   = (float*)(smem + SM_META + 1024);

    const float* Aptr = (ROWSHIFT == 1) ? Asrc : g_act;
    float*       Cptr = SQRELU ? g_act : g_y;

    if (tid < BM) {
        int idx = m0 + tid;
        int aid = g_rows[e][idx < cnt ? idx : cnt - 1];
        s_a[tid]   = aid;
        s_row[tid] = aid >> ROWSHIFT;
        if (GATE) s_g[tid] = g_gate[aid];
    }
    __syncthreads();

    const float* Bslab = Bsrc + (size_t)e * CSTRIDE * KTOT + (size_t)n0 * KTOT;

    // ---- staging precompute ----
    // Wave 1 handles true ks 0..3 (kq 0..7); wave 2 handles true ks 4..7.
    // A swizzle is ks-dependent => separate full offsets per wave.
    const float* asrc[2]; uint32_t aoff[2], aoff2[2];
    const float* bsrc[4]; uint32_t boff[4];
#pragma unroll
    for (int i = 0; i < 2; i++) {
        int c4  = tid + THREADS * i;
        int row = c4 >> 3, kq = c4 & 7;
        int ks = kq >> 1, p = kq & 1;
        int MI = row >> 4, h = (row >> 3) & 1, gg = row & 7;
        int ge1 = gg ^ (ks >> 1);            // true ks = ks      -> sw 0/1
        int ge2 = gg ^ ((ks >> 1) | 2);      // true ks = ks + 4  -> sw 2/3
        aoff[i]  = (uint32_t)(((MI * 8 + ks)     * 33 + 4 * ge1) * 16 + (h + 2 * p) * 4);
        aoff2[i] = (uint32_t)(((MI * 8 + ks + 4) * 33 + 4 * ge2) * 16 + (h + 2 * p) * 4);
        asrc[i] = Aptr + (size_t)s_row[row] * KTOT + 4 * kq;
    }
#pragma unroll
    for (int i = 0; i < 4; i++) {
        int c4  = tid + THREADS * i;
        int row = c4 >> 3, kq = c4 & 7;
        int ks = kq >> 1, p = kq & 1;
        int NI = row >> 3, gg = row & 7;
        boff[i] = (uint32_t)(((NI * 8 + ks) * 33 + 4 * gg) * 8 + p * 4);
        bsrc[i] = Bslab + (size_t)row * KTOT + 4 * kq;
    }

    float4 ra[2], rb[4];
    auto LDG = [&](int c, int w) {           // w = wave (0/1)
        const int k0 = c * BK + w * 32;
#pragma unroll
        for (int i = 0; i < 2; i++) ra[i] = *(const float4*)(asrc[i] + k0);
#pragma unroll
        for (int i = 0; i < 4; i++) rb[i] = *(const float4*)(bsrc[i] + k0);
    };
    auto STS = [&](int s, int w) {           // s = buffer parity, w = wave
        char* stA = smem + s * STAGE_BYTES;
        char* stB = smem + s * STAGE_BYTES + A_BUF_BYTES + w * B_W2_OFF;
        const uint32_t* ao = w ? aoff2 : aoff;
#pragma unroll
        for (int i = 0; i < 2; i++) {
            const float* v = &ra[i].x;
#pragma unroll
            for (int j = 0; j < 4; j++)
                *(uint32_t*)(stA + ao[i] + j * 16) = f2tf(v[j]);
        }
#pragma unroll
        for (int i = 0; i < 4; i++) {
            const float* v = &rb[i].x;
#pragma unroll
            for (int j = 0; j < 4; j++)
                *(uint32_t*)(stB + boff[i] + j * 8) = f2tf(v[j]);
        }
    };

    float cacc[4][4][4];
#pragma unroll
    for (int mi = 0; mi < 4; mi++)
#pragma unroll
        for (int ni = 0; ni < 4; ni++)
#pragma unroll
            for (int r = 0; r < 4; r++) cacc[mi][ni][r] = 0.f;

    // one half-chunk of MMAs: ks = ksbase..ksbase+3 on buffer parity s
    auto COMPUTE = [&](int s, int ksbase) {
        const char* Abuf = smem + s * STAGE_BYTES;
        const char* Bbuf = Abuf + A_BUF_BYTES;
#pragma unroll
        for (int kk = 0; kk < 4; kk++) {
            const int ks = ksbase + kk;
            const int laneA = lane ^ ((ks >> 1) << 2);
            uint4 af[4]; uint2 bf[4];
#pragma unroll
            for (int mi = 0; mi < 4; mi++) {
                int MI = wm * 4 + mi;
                af[mi] = *(const uint4*)(Abuf + ((MI * 8 + ks) * 33 + laneA) * 16);
            }
#pragma unroll
            for (int ni = 0; ni < 4; ni++) {
                int NI = wn * 4 + ni;
                bf[ni] = *(const uint2*)(Bbuf + ((NI * 8 + ks) * 33 + lane) * 8);
            }
#pragma unroll
            for (int mi = 0; mi < 4; mi++)
#pragma unroll
                for (int ni = 0; ni < 4; ni++)
                    mma_tf32(cacc[mi][ni], &af[mi].x, &bf[ni].x);
        }
    };

    constexpr int NC = KTOT / BK;
    // prologue: fill buffer 0 (both waves)
    LDG(0, 0); STS(0, 0);
    LDG(0, 1); STS(0, 1);
    __syncthreads();

    for (int c = 0; c < NC; c++) {
        const int s  = c & 1;
        const int sn = (c + 1) & 1;
        if (c + 1 < NC) LDG(c + 1, 0);       // wave-1 prefetch

        COMPUTE(s, 0);                        // ks 0..3

        if (c + 1 < NC) {
            STS(sn, 0);                       // wave-1 store -> other buffer
            LDG(c + 1, 1);                    // wave-2 prefetch
        }

        COMPUTE(s, 4);                        // ks 4..7

        if (c + 1 < NC) STS(sn, 1);           // wave-2 store
        __syncthreads();
    }

    // ---- epilogue: direct STG from accumulators ----
#pragma unroll
    for (int mi = 0; mi < 4; mi++) {
#pragma unroll
        for (int ni = 0; ni < 4; ni++) {
            const float* c = cacc[mi][ni];
            int rb_ = wm * 64 + mi * 16;
            int cb  = wn * 32 + ni * 8 + 2 * t;
#pragma unroll
            for (int h = 0; h < 2; h++) {
                int r = rb_ + g + h * 8;
                if (m0 + r < cnt) {
                    int aid = s_a[r];
                    float gv = GATE ? s_g[r] : 0.f;
#pragma unroll
                    for (int q = 0; q < 2; q++) {
                        float v = c[h * 2 + q];
                        if (SQRELU) v = (v > 0.f) ? v * v : 0.f;
                        if (GATE) v *= gv;
                        Cptr[(size_t)aid * CSTRIDE + n0 + cb + q] = v;
                    }
                }
            }
        }
    }
}

// ---------------- kernel 4: combine the two gated expert outputs -----------
__global__ void k_combine(float* __restrict__ out) {
    int i = blockIdx.x * blockDim.x + threadIdx.x;
    if (i >= NTOK * DDIM / 4) return;
    int n  = i / (DDIM / 4);
    int d4 = i % (DDIM / 4);
    const float4 a = *((const float4*)(g_y + (size_t)(2 * n) * DDIM) + d4);
    const float4 b = *((const float4*)(g_y + (size_t)(2 * n + 1) * DDIM) + d4);
    float4 o;
    o.x = a.x + b.x;
    o.y = a.y + b.y;
    o.z = a.z + b.z;
    o.w = a.w + b.w;
    *((float4*)(out + (size_t)n * DDIM) + d4) = o;
}

// ---------------- launch ----------------------------------------------------
extern "C" void kernel_launch(void* const* d_in, const int* in_sizes, int n_in,
                              void* d_out, int out_size) {
    const float* x  = (const float*)d_in[0];   // [2048, 1024]
    const float* Wr = (const float*)d_in[1];   // [8, 1024]
    const float* W1 = (const float*)d_in[2];   // [8, 2048, 1024]
    const float* W2 = (const float*)d_in[3];   // [8, 1024, 2048]
    float* out = (float*)d_out;                // [2048, 1024]
    (void)in_sizes; (void)n_in; (void)out_size;

    cudaFuncSetAttribute((const void*)k_gemm<DDIM, 1, FDIM, true, false>,
                         cudaFuncAttributeMaxDynamicSharedMemorySize, SM_TOTAL);
    cudaFuncSetAttribute((const void*)k_gemm<FDIM, 0, DDIM, false, true>,
                         cudaFuncAttributeMaxDynamicSharedMemorySize, SM_TOTAL);

    k_zero<<<1, 32>>>();
    k_router<<<NTOK / 8, 256>>>(x, Wr);

    // fc1: act[a, f] = relu(x[a>>1] . W1[e][f])^2
    k_gemm<DDIM, 1, FDIM, true, false>
        <<<dim3(FDIM / BN, NTOK / BM, NEXP), THREADS, SM_TOTAL>>>(x, W1);

    // fc2: y[a, d] = gate[a] * (act[a] . W2[e][d])
    k_gemm<FDIM, 0, DDIM, false, true>
        <<<dim3(DDIM / BN, NTOK / BM, NEXP), THREADS, SM_TOTAL>>>(nullptr, W2);

    k_combine<<<(NTOK * DDIM / 4 + 255) / 256, 256>>>(out);
}

// round 14
// speedup vs baseline: 1.5496x; 1.5496x over previous
#include <cuda_runtime.h>
#include <cuda_fp16.h>
#include <math.h>
#include <stdint.h>

#define NTOK 2048
#define DDIM 1024
#define NEXP 8
#define FDIM 2048
#define NASS (NTOK * 2)

// GEMM tiling: CTA 128x256, warp 64x32 (16 warps = 512 threads), BK=32
#define BM 128
#define BN 256
#define BK 32
#define THREADS 512

// fp16 fragment-major smem (double-buffered), m16n8k16 => 2 ks-slices per BK=32
//  A: 16 groups (MI 0..7 x ks 0..1), each 33 lines x 16B (line = lane's 4-reg frag)
//  B: 64 groups (NI 0..31 x ks 0..1), each 33 lines x 8B
#define A_GRP_BYTES (33 * 16)
#define B_GRP_BYTES (33 * 8)
#define A_BUF_BYTES (16 * A_GRP_BYTES)      // 8448
#define B_BUF_BYTES (64 * B_GRP_BYTES)      // 16896
#define STAGE_BYTES (A_BUF_BYTES + B_BUF_BYTES)   // 25344
#define SM_META     (2 * STAGE_BYTES)             // 50688
#define SM_TOTAL    (SM_META + 512 * 3)           // 52224

// ---------------- scratch (device globals) ---------------------------------
__device__ int   g_cnt[NEXP];
__device__ int   g_rows[NEXP][NTOK];
__device__ float g_gate[NASS];
__device__ float g_act[(size_t)NASS * FDIM];   // 32 MB
__device__ float g_y[(size_t)NASS * DDIM];     // 16 MB

// ---------------- helpers ---------------------------------------------------
__device__ __forceinline__ uint32_t f2h2(float a, float b) {   // packed rn half2
    __half2 h = __floats2half2_rn(a, b);
    return *(uint32_t*)&h;
}
__device__ __forceinline__ void mma_f16(float* c, const unsigned* a, const unsigned* b) {
    asm volatile(
        "mma.sync.aligned.m16n8k16.row.col.f32.f16.f16.f32 "
        "{%0,%1,%2,%3}, {%4,%5,%6,%7}, {%8,%9}, {%0,%1,%2,%3};"
        : "+f"(c[0]), "+f"(c[1]), "+f"(c[2]), "+f"(c[3])
        : "r"(a[0]), "r"(a[1]), "r"(a[2]), "r"(a[3]), "r"(b[0]), "r"(b[1]));
}

// ---------------- kernel 0: zero expert counters ---------------------------
__global__ void k_zero() {
    if (threadIdx.x < NEXP) g_cnt[threadIdx.x] = 0;
}

// ---------------- kernel 1: router (one warp per token) --------------------
__global__ void k_router(const float* __restrict__ x, const float* __restrict__ Wr) {
    int warp = (blockIdx.x * blockDim.x + threadIdx.x) >> 5;
    int lane = threadIdx.x & 31;
    if (warp >= NTOK) return;
    const float* xr = x + (size_t)warp * DDIM;

    float acc[NEXP];
#pragma unroll
    for (int e = 0; e < NEXP; e++) acc[e] = 0.f;
    for (int i = lane; i < DDIM; i += 32) {
        float xv = xr[i];
#pragma unroll
        for (int e = 0; e < NEXP; e++) acc[e] += xv * Wr[e * DDIM + i];
    }
#pragma unroll
    for (int e = 0; e < NEXP; e++) {
#pragma unroll
        for (int off = 16; off; off >>= 1)
            acc[e] += __shfl_xor_sync(0xffffffffu, acc[e], off);
    }
    if (lane == 0) {
        int i0 = 0;
#pragma unroll
        for (int e = 1; e < NEXP; e++)
            if (acc[e] > acc[i0]) i0 = e;
        int i1 = -1;
#pragma unroll
        for (int e = 0; e < NEXP; e++) {
            if (e == i0) continue;
            if (i1 < 0 || acc[e] > acc[i1]) i1 = e;
        }
        float ex  = expf(acc[i1] - acc[i0]);
        float inv = 1.f / (1.f + ex);
        int p0 = atomicAdd(&g_cnt[i0], 1);
        g_rows[i0][p0] = 2 * warp;
        int p1 = atomicAdd(&g_cnt[i1], 1);
        g_rows[i1][p1] = 2 * warp + 1;
        g_gate[2 * warp]     = inv;
        g_gate[2 * warp + 1] = ex * inv;
    }
}

// ---------------- grouped GEMM: fp16 m16n8k16, f32 accumulate --------------
// CTA 128x256; 16 warps 2(m) x 8(n); warp 64x32. BK=32, double-buffered.
// A-frag layout (per group MI,ks): line ℓ = lane holds its 4 regs contiguously:
//   bytes 0,4,8,12 = (row g,k 2t..2t+1), (row g+8, same), (row g,+8), (row g+8,+8)
// B-frag: line ℓ bytes 0,4 = (k 2t..2t+1, n=g), (k 2t+8..2t+9, n=g)
template <int KTOT, int ROWSHIFT, int CSTRIDE, bool SQRELU, bool GATE>
__global__ __launch_bounds__(THREADS, 1)
void k_gemm(const float* __restrict__ Asrc, const float* __restrict__ Bsrc) {
    extern __shared__ char smem[];
    const int e   = blockIdx.z;
    const int cnt = g_cnt[e];
    const int m0  = blockIdx.y * BM;
    if (m0 >= cnt) return;
    const int n0  = blockIdx.x * BN;
    const int tid  = threadIdx.x;
    const int wid  = tid >> 5;
    const int lane = tid & 31;
    const int g    = lane >> 2;
    const int t    = lane & 3;
    const int wm   = wid >> 3;     // 0..1
    const int wn   = wid & 7;      // 0..7

    int*   s_a   = (int*)(smem + SM_META);
    int*   s_row = (int*)(smem + SM_META + 512);
    float* s_g   = (float*)(smem + SM_META + 1024);

    const float* Aptr = (ROWSHIFT == 1) ? Asrc : g_act;
    float*       Cptr = SQRELU ? g_act : g_y;

    if (tid < BM) {
        int idx = m0 + tid;
        int aid = g_rows[e][idx < cnt ? idx : cnt - 1];
        s_a[tid]   = aid;
        s_row[tid] = aid >> ROWSHIFT;
        if (GATE) s_g[tid] = g_gate[aid];
    }
    __syncthreads();

    const float* Bslab = Bsrc + (size_t)e * CSTRIDE * KTOT + (size_t)n0 * KTOT;

    // ---- staging precompute ----
    // float4 chunk c4: row = c4>>3, kq = c4&7 (k = 4kq..4kq+3 within BK=32)
    // ks = kq>>2 (K16 slice), q2 = kq&3 -> k-pairs p = 2q2, 2q2+1 (same hi = q2>>1)
    // A: 1024 chunks -> 2/thread ; B: 2048 chunks -> 4/thread
    const float* asrc[2]; uint32_t aoff[2];
    const float* bsrc[4]; uint32_t boff[4];
#pragma unroll
    for (int i = 0; i < 2; i++) {
        int c4  = tid + THREADS * i;
        int row = c4 >> 3, kq = c4 & 7;
        int ks = kq >> 2, q2 = kq & 3;
        int t0 = (2 * q2) & 3, hi = q2 >> 1;
        int MI = row >> 4, h = (row >> 3) & 1, gg = row & 7;
        aoff[i] = (uint32_t)((MI * 2 + ks) * A_GRP_BYTES
                             + (4 * gg + t0) * 16 + h * 4 + hi * 8);
        asrc[i] = Aptr + (size_t)s_row[row] * KTOT + 4 * kq;
    }
#pragma unroll
    for (int i = 0; i < 4; i++) {
        int c4  = tid + THREADS * i;
        int row = c4 >> 3, kq = c4 & 7;
        int ks = kq >> 2, q2 = kq & 3;
        int t0 = (2 * q2) & 3, hi = q2 >> 1;
        int NI = row >> 3, gg = row & 7;
        boff[i] = (uint32_t)((NI * 2 + ks) * B_GRP_BYTES
                             + (4 * gg + t0) * 8 + hi * 4);
        bsrc[i] = Bslab + (size_t)row * KTOT + 4 * kq;
    }

    float4 ra[2], rb[4];
    auto LDG = [&](int c) {
        const int k0 = c * BK;
#pragma unroll
        for (int i = 0; i < 2; i++) ra[i] = *(const float4*)(asrc[i] + k0);
#pragma unroll
        for (int i = 0; i < 4; i++) rb[i] = *(const float4*)(bsrc[i] + k0);
    };
    auto STS = [&](int s) {          // s = buffer parity
        char* stA = smem + s * STAGE_BYTES;
        char* stB = stA + A_BUF_BYTES;
#pragma unroll
        for (int i = 0; i < 2; i++) {
            *(uint32_t*)(stA + aoff[i])      = f2h2(ra[i].x, ra[i].y);
            *(uint32_t*)(stA + aoff[i] + 16) = f2h2(ra[i].z, ra[i].w);  // next line
        }
#pragma unroll
        for (int i = 0; i < 4; i++) {
            *(uint32_t*)(stB + boff[i])     = f2h2(rb[i].x, rb[i].y);
            *(uint32_t*)(stB + boff[i] + 8) = f2h2(rb[i].z, rb[i].w);   // next line
        }
    };

    float cacc[4][4][4];
#pragma unroll
    for (int mi = 0; mi < 4; mi++)
#pragma unroll
        for (int ni = 0; ni < 4; ni++)
#pragma unroll
            for (int r = 0; r < 4; r++) cacc[mi][ni][r] = 0.f;

    constexpr int NC = KTOT / BK;
    LDG(0);
    STS(0);
    __syncthreads();

    for (int c = 0; c < NC; c++) {
        if (c + 1 < NC) LDG(c + 1);      // prefetch next chunk into registers

        const char* Abuf = smem + (c & 1) * STAGE_BYTES;
        const char* Bbuf = Abuf + A_BUF_BYTES;
#pragma unroll
        for (int ks = 0; ks < 2; ks++) {
            uint4 af[4]; uint2 bf[4];
#pragma unroll
            for (int mi = 0; mi < 4; mi++) {
                int grp = (wm * 4 + mi) * 2 + ks;
                af[mi] = *(const uint4*)(Abuf + grp * A_GRP_BYTES + lane * 16);
            }
#pragma unroll
            for (int ni = 0; ni < 4; ni++) {
                int grp = (wn * 4 + ni) * 2 + ks;
                bf[ni] = *(const uint2*)(Bbuf + grp * B_GRP_BYTES + lane * 8);
            }
#pragma unroll
            for (int mi = 0; mi < 4; mi++)
#pragma unroll
                for (int ni = 0; ni < 4; ni++)
                    mma_f16(cacc[mi][ni], &af[mi].x, &bf[ni].x);
        }

        if (c + 1 < NC) STS((c + 1) & 1);   // other buffer; readers done at sync(c-1)
        __syncthreads();
    }

    // ---- epilogue: direct STG from accumulators ----
#pragma unroll
    for (int mi = 0; mi < 4; mi++) {
#pragma unroll
        for (int ni = 0; ni < 4; ni++) {
            const float* c = cacc[mi][ni];
            int rb_ = wm * 64 + mi * 16;
            int cb  = wn * 32 + ni * 8 + 2 * t;
#pragma unroll
            for (int h = 0; h < 2; h++) {
                int r = rb_ + g + h * 8;
                if (m0 + r < cnt) {
                    int aid = s_a[r];
                    float gv = GATE ? s_g[r] : 0.f;
#pragma unroll
                    for (int q = 0; q < 2; q++) {
                        float v = c[h * 2 + q];
                        if (SQRELU) v = (v > 0.f) ? v * v : 0.f;
                        if (GATE) v *= gv;
                        Cptr[(size_t)aid * CSTRIDE + n0 + cb + q] = v;
                    }
                }
            }
        }
    }
}

// ---------------- kernel 4: combine the two gated expert outputs -----------
__global__ void k_combine(float* __restrict__ out) {
    int i = blockIdx.x * blockDim.x + threadIdx.x;
    if (i >= NTOK * DDIM / 4) return;
    int n  = i / (DDIM / 4);
    int d4 = i % (DDIM / 4);
    const float4 a = *((const float4*)(g_y + (size_t)(2 * n) * DDIM) + d4);
    const float4 b = *((const float4*)(g_y + (size_t)(2 * n + 1) * DDIM) + d4);
    float4 o;
    o.x = a.x + b.x;
    o.y = a.y + b.y;
    o.z = a.z + b.z;
    o.w = a.w + b.w;
    *((float4*)(out + (size_t)n * DDIM) + d4) = o;
}

// ---------------- launch ----------------------------------------------------
extern "C" void kernel_launch(void* const* d_in, const int* in_sizes, int n_in,
                              void* d_out, int out_size) {
    const float* x  = (const float*)d_in[0];   // [2048, 1024]
    const float* Wr = (const float*)d_in[1];   // [8, 1024]
    const float* W1 = (const float*)d_in[2];   // [8, 2048, 1024]
    const float* W2 = (const float*)d_in[3];   // [8, 1024, 2048]
    float* out = (float*)d_out;                // [2048, 1024]
    (void)in_sizes; (void)n_in; (void)out_size;

    cudaFuncSetAttribute((const void*)k_gemm<DDIM, 1, FDIM, true, false>,
                         cudaFuncAttributeMaxDynamicSharedMemorySize, SM_TOTAL);
    cudaFuncSetAttribute((const void*)k_gemm<FDIM, 0, DDIM, false, true>,
                         cudaFuncAttributeMaxDynamicSharedMemorySize, SM_TOTAL);

    k_zero<<<1, 32>>>();
    k_router<<<NTOK / 8, 256>>>(x, Wr);

    // fc1: act[a, f] = relu(x[a>>1] . W1[e][f])^2
    k_gemm<DDIM, 1, FDIM, true, false>
        <<<dim3(FDIM / BN, NTOK / BM, NEXP), THREADS, SM_TOTAL>>>(x, W1);

    // fc2: y[a, d] = gate[a] * (act[a] . W2[e][d])
    k_gemm<FDIM, 0, DDIM, false, true>
        <<<dim3(DDIM / BN, NTOK / BM, NEXP), THREADS, SM_TOTAL>>>(nullptr, W2);

    k_combine<<<(NTOK * DDIM / 4 + 255) / 256, 256>>>(out);
}